// round 12
// baseline (speedup 1.0000x reference)
#include <cuda_runtime.h>
#include <math.h>

#define BB   8
#define CC   64
#define CR   8
#define HH   64
#define WWD  64
#define NPIX 4096   // HH*WWD
#define NBLK 128    // k_rest grid: <= SM count; 128 = BB*16 chunks
#define NTHR 1024

// ---------------- device scratch (static, no allocation) ----------------
__device__ float d_avg[BB * CC];    // per-(b,c) mean
__device__ float d_maxv[BB * CC];   // per-(b,c) max
// PAM fallback scratch (only written when gamma != 0)
__device__ float d_q[BB * CR * NPIX];
__device__ float d_k[BB * CR * NPIX];
__device__ float d_v[BB * CC * NPIX];
__device__ __align__(16) float d_pam[BB * CC * NPIX];
// grid barrier ticket (used ONLY by the g!=0 fallback inside k_rest)
__device__ unsigned long long g_bar;

__device__ __forceinline__ void grid_barrier() {
    __syncthreads();
    if (threadIdx.x == 0) {
        __threadfence();
        const unsigned long long t = atomicAdd(&g_bar, 1ULL);
        const unsigned long long release = (t / NBLK + 1ULL) * (unsigned long long)NBLK;
        volatile unsigned long long* p = &g_bar;
        while (*p < release) { }
    }
    __syncthreads();
}

// ================= Node 1: per-(b,c) mean & max over HW =================
__global__ void __launch_bounds__(256, 4)
k_stats(const float* __restrict__ x) {
    const int bc = blockIdx.x;                 // 0 .. 511
    const float4* xp = reinterpret_cast<const float4*>(x + (size_t)bc * NPIX);
    const int t = threadIdx.x;
    float s = 0.0f, m = -INFINITY;
    #pragma unroll
    for (int j = 0; j < 4; j++) {
        const float4 v = xp[t + j * 256];
        s += (v.x + v.y) + (v.z + v.w);
        m = fmaxf(m, fmaxf(fmaxf(v.x, v.y), fmaxf(v.z, v.w)));
    }
    #pragma unroll
    for (int off = 16; off; off >>= 1) {
        s += __shfl_down_sync(0xffffffffu, s, off);
        m  = fmaxf(m, __shfl_down_sync(0xffffffffu, m, off));
    }
    __shared__ float ss[8], sm[8];
    const int wid = t >> 5, lid = t & 31;
    if (lid == 0) { ss[wid] = s; sm[wid] = m; }
    __syncthreads();
    if (t == 0) {
        float ts = 0.0f, tm = -INFINITY;
        #pragma unroll
        for (int i = 0; i < 8; i++) { ts += ss[i]; tm = fmaxf(tm, sm[i]); }
        d_avg[bc]  = ts * (1.0f / NPIX);
        d_maxv[bc] = tm;
    }
}

// ====== Node 2: MLP + halo spatial stats + conv + final (no grid sync) ======
__global__ void __launch_bounds__(NTHR, 1)
k_rest(const float* __restrict__ x,
       const float* __restrict__ fc1,   // [CR, C]
       const float* __restrict__ fc2,   // [C, CR]
       const float* __restrict__ qw, const float* __restrict__ qbias,
       const float* __restrict__ kw, const float* __restrict__ kbias,
       const float* __restrict__ vw, const float* __restrict__ vbias,
       const float* __restrict__ gamma,
       const float* __restrict__ sw,    // [2,7,7]
       float* __restrict__ out) {
    const int blk = blockIdx.x;   // 0..127
    const int t   = threadIdx.x;  // 0..1023
    const int b     = blk >> 4;   // batch
    const int chunk = blk & 15;   // 4-row chunk
    const int n0    = chunk << 8;
    const int h0    = chunk << 2;

    // dynamic smem 84 KB:
    //   [0 .. 64KB)  sx[c][256]      x stash for own 4 rows
    //   [64 .. 74KB) ps_h[4][640]    halo-stats partial sums
    //   [74 .. 84KB) pm_h[4][640]    halo-stats partial maxes
    // PAM fallback overlays att[4096]+red[1024] on the partials region (20KB),
    // so the sx stash stays valid for the final combine.
    extern __shared__ __align__(16) float dyn[];
    float* sx   = dyn;                       // [CC * 256]
    float* ps_h = dyn + CC * 256;            // [4 * 640]
    float* pm_h = dyn + CC * 256 + 4 * 640;  // [4 * 640]
    float* att  = dyn + CC * 256;            // fallback only [4096]
    float* red  = dyn + CC * 256 + NPIX;     // fallback only [1024]

    __shared__ float s_sum[CC], s_max[CC], ca[CC];
    __shared__ float tile_avg[10][70], tile_max[10][70];
    __shared__ float wgt[98];
    __shared__ __align__(16) float mask_s[256];
    __shared__ __align__(16) float cpart[NTHR];

    const float g = gamma[0];

    // ---- preload channel stats + weights ----
    if (t < 98) wgt[t] = sw[t];
    if (t >= 128 && t < 192) {
        s_sum[t - 128] = __ldcg(&d_avg[b * CC + (t - 128)]);
        s_max[t - 128] = __ldcg(&d_maxv[b * CC + (t - 128)]);
    }
    // zero conv tile (columns 0-2 / 67-69 stay zero as padding)
    for (int i = t; i < 700; i += NTHR) {
        (&tile_avg[0][0])[i] = 0.0f;
        (&tile_max[0][0])[i] = 0.0f;
    }
    __syncthreads();

    // ---- tiny MLP on warp 0 -> ca ----
    if (t < 32) {
        float h = 0.0f;
        if (t < CR) {
            float ha = 0.0f, hm = 0.0f;
            #pragma unroll
            for (int c = 0; c < CC; c++) {
                const float w = fc1[t * CC + c];
                ha += s_sum[c] * w;
                hm += s_max[c] * w;
            }
            h = fmaxf(ha, 0.0f) + fmaxf(hm, 0.0f);
        }
        float o0 = 0.0f, o1 = 0.0f;
        #pragma unroll
        for (int r = 0; r < CR; r++) {
            const float hr = __shfl_sync(0xffffffffu, h, r);
            o0 += hr * fc2[t * CR + r];
            o1 += hr * fc2[(t + 32) * CR + r];
        }
        ca[t]      = 1.0f / (1.0f + __expf(-o0));
        ca[t + 32] = 1.0f / (1.0f + __expf(-o1));
    }
    __syncthreads();

    // ---- halo spatial stats over 10 rows (640 px), x-stash for own 4 rows ----
    // work items: 640 px * 4 channel-groups = 2560; each handles 16 channels.
    {
        const int rowlo = h0 - 3;          // global row of halo row 0
        #pragma unroll
        for (int it = 0; it < 3; it++) {   // ceil(2560/1024)=3; last partial
            const int i = t + it * NTHR;
            if (i < 2560) {
                const int px  = i >> 2;    // 0..639 halo pixel
                const int grp = i & 3;     // channel group
                const int r   = px >> 6;   // halo row 0..9
                const int col = px & 63;
                const int gh  = rowlo + r;
                float s = 0.0f, m = 0.0f;  // 0 = zero-padding for OOB rows
                if ((unsigned)gh < (unsigned)HH) {
                    const float* xb = x + (size_t)b * CC * NPIX + gh * WWD + col;
                    const bool stash = (r >= 3 && r < 7);
                    const int  lpx   = (r - 3) * 64 + col;
                    m = -INFINITY;
                    #pragma unroll
                    for (int cc = 0; cc < 16; cc++) {
                        const int c = grp * 16 + cc;
                        const float xv = __ldg(&xb[c * NPIX]);
                        if (stash) sx[c * 256 + lpx] = xv;
                        const float v = xv * ca[c];
                        s += v;
                        m = fmaxf(m, v);
                    }
                }
                ps_h[grp * 640 + px] = s;
                pm_h[grp * 640 + px] = m;
            }
        }
    }
    __syncthreads();
    if (t < 640) {
        const int r = t >> 6, col = t & 63;
        const int gh = h0 - 3 + r;
        float ts = 0.0f, tm = 0.0f;        // zero padding for OOB rows
        if ((unsigned)gh < (unsigned)HH) {
            ts = (ps_h[t] + ps_h[640 + t] + ps_h[1280 + t] + ps_h[1920 + t])
                 * (1.0f / CC);
            tm = fmaxf(fmaxf(pm_h[t], pm_h[640 + t]),
                       fmaxf(pm_h[1280 + t], pm_h[1920 + t]));
        }
        tile_avg[r][col + 3] = ts;
        tile_max[r][col + 3] = tm;
    }
    __syncthreads();

    // ============ PAM fallback (uniform branch; benchmark: g==0) =============
    if (g != 0.0f) {
        for (int bn = blk * NTHR + t; bn < BB * NPIX; bn += NBLK * NTHR) {
            const int bb = bn >> 12, n = bn & (NPIX - 1);
            const float* xb = x + (size_t)bb * CC * NPIX + n;
            float qa[CR], ka[CR];
            #pragma unroll
            for (int r = 0; r < CR; r++) { qa[r] = qbias[r]; ka[r] = kbias[r]; }
            for (int c = 0; c < CC; c++) {
                const float xv = xb[c * NPIX];
                #pragma unroll
                for (int r = 0; r < CR; r++) {
                    qa[r] += xv * qw[r * CC + c];
                    ka[r] += xv * kw[r * CC + c];
                }
            }
            #pragma unroll
            for (int r = 0; r < CR; r++) {
                d_q[(bb * CR + r) * NPIX + n] = qa[r];
                d_k[(bb * CR + r) * NPIX + n] = ka[r];
            }
        }
        for (int bcn = blk * NTHR + t; bcn < BB * CC * NPIX; bcn += NBLK * NTHR) {
            const int bc = bcn >> 12;
            const int bb = bc >> 6, c = bc & 63, n = bcn & (NPIX - 1);
            const float* xb = x + (size_t)bb * CC * NPIX + n;
            float acc = vbias[c];
            for (int cc = 0; cc < CC; cc++) acc += xb[cc * NPIX] * vw[c * CC + cc];
            d_v[bcn] = acc;
        }
        grid_barrier();
        for (int row = blk; row < BB * NPIX; row += NBLK) {
            const int bb = row >> 12;
            const int i  = row & (NPIX - 1);
            float qr[CR];
            #pragma unroll
            for (int r = 0; r < CR; r++) qr[r] = __ldcg(&d_q[(bb * CR + r) * NPIX + i]);
            float mx = -INFINITY;
            for (int j = t; j < NPIX; j += NTHR) {
                float e = 0.0f;
                #pragma unroll
                for (int r = 0; r < CR; r++) e += qr[r] * __ldcg(&d_k[(bb * CR + r) * NPIX + j]);
                att[j] = e;
                mx = fmaxf(mx, e);
            }
            red[t] = mx; __syncthreads();
            for (int s = NTHR / 2; s; s >>= 1) {
                if (t < s) red[t] = fmaxf(red[t], red[t + s]);
                __syncthreads();
            }
            mx = red[0]; __syncthreads();
            float sum = 0.0f;
            for (int j = t; j < NPIX; j += NTHR) {
                const float e = expf(att[j] - mx);
                att[j] = e;
                sum += e;
            }
            red[t] = sum; __syncthreads();
            for (int s = NTHR / 2; s; s >>= 1) {
                if (t < s) red[t] += red[t + s];
                __syncthreads();
            }
            const float inv = 1.0f / red[0]; __syncthreads();
            for (int c = 0; c < CC; c++) {
                float acc = 0.0f;
                for (int j = t; j < NPIX; j += NTHR)
                    acc += att[j] * __ldcg(&d_v[(bb * CC + c) * NPIX + j]);
                red[t] = acc; __syncthreads();
                for (int s = NTHR / 2; s; s >>= 1) {
                    if (t < s) red[t] += red[t + s];
                    __syncthreads();
                }
                if (t == 0) d_pam[(bb * CC + c) * NPIX + i] = red[0] * inv;
                __syncthreads();
            }
        }
        grid_barrier();
    }

    // ---- 7x7 conv (4 threads/px) + sigmoid ----
    {
        const int px = t >> 2, q = t & 3;
        const int h = px >> 6, w = px & 63;
        float acc = 0.0f;
        {
            const int kh = q;
            #pragma unroll
            for (int kw2 = 0; kw2 < 7; kw2++)
                acc += tile_avg[h + kh][w + kw2] * wgt[kh * 7 + kw2]
                     + tile_max[h + kh][w + kw2] * wgt[49 + kh * 7 + kw2];
        }
        if (q < 3) {
            const int kh = q + 4;
            #pragma unroll
            for (int kw2 = 0; kw2 < 7; kw2++)
                acc += tile_avg[h + kh][w + kw2] * wgt[kh * 7 + kw2]
                     + tile_max[h + kh][w + kw2] * wgt[49 + kh * 7 + kw2];
        }
        cpart[px * 4 + q] = acc;
    }
    __syncthreads();
    if (t < 256) {
        const float4 cp = reinterpret_cast<const float4*>(cpart)[t];
        mask_s[t] = 1.0f / (1.0f + __expf(-((cp.x + cp.y) + (cp.z + cp.w))));
    }
    __syncthreads();

    // ---- final combine: x from smem stash ----
    {
        const int px4 = t & 63;
        const int c0  = t >> 6;
        const float4 m4 = reinterpret_cast<const float4*>(mask_s)[px4];
        const size_t base4 = (size_t)b * CC * (NPIX / 4) + (size_t)(n0 >> 2) + px4;
        if (g == 0.0f) {
            #pragma unroll
            for (int k = 0; k < 4; k++) {
                const int c = c0 + 16 * k;
                const float4 xv = reinterpret_cast<const float4*>(&sx[c * 256])[px4];
                const float cav = ca[c];
                float4 o;
                o.x = xv.x * (1.0f + cav * m4.x);
                o.y = xv.y * (1.0f + cav * m4.y);
                o.z = xv.z * (1.0f + cav * m4.z);
                o.w = xv.w * (1.0f + cav * m4.w);
                reinterpret_cast<float4*>(out)[base4 + (size_t)c * (NPIX / 4)] = o;
            }
        } else {
            #pragma unroll
            for (int k = 0; k < 4; k++) {
                const int c = c0 + 16 * k;
                const size_t idx4 = base4 + (size_t)c * (NPIX / 4);
                const float4 xv = reinterpret_cast<const float4*>(&sx[c * 256])[px4];
                const float4 pv = reinterpret_cast<const float4*>(d_pam)[idx4];
                const float cav = ca[c];
                float4 o;
                o.x = xv.x * (1.0f + cav * m4.x) + g * pv.x;
                o.y = xv.y * (1.0f + cav * m4.y) + g * pv.y;
                o.z = xv.z * (1.0f + cav * m4.z) + g * pv.z;
                o.w = xv.w * (1.0f + cav * m4.w) + g * pv.w;
                reinterpret_cast<float4*>(out)[idx4] = o;
            }
        }
    }
}

// ---------------- launch ----------------
extern "C" void kernel_launch(void* const* d_in, const int* in_sizes, int n_in,
                              void* d_out, int out_size) {
    const float* x     = (const float*)d_in[0];
    const float* fc1_w = (const float*)d_in[1];
    const float* fc2_w = (const float*)d_in[2];
    const float* q_w   = (const float*)d_in[3];
    const float* q_b   = (const float*)d_in[4];
    const float* k_w   = (const float*)d_in[5];
    const float* k_b   = (const float*)d_in[6];
    const float* v_w   = (const float*)d_in[7];
    const float* v_b   = (const float*)d_in[8];
    const float* gamma = (const float*)d_in[9];
    const float* sa_w  = (const float*)d_in[10];
    float* out = (float*)d_out;

    const int dyn_bytes = (CC * 256 + 2 * 4 * 640) * (int)sizeof(float);   // 84 KB
    cudaFuncSetAttribute(k_rest, cudaFuncAttributeMaxDynamicSharedMemorySize, dyn_bytes);

    k_stats<<<BB * CC, 256>>>(x);
    k_rest<<<NBLK, NTHR, dyn_bytes>>>(x, fc1_w, fc2_w, q_w, q_b, k_w, k_b,
                                      v_w, v_b, gamma, sa_w, out);
}

// round 13
// speedup vs baseline: 1.3341x; 1.3341x over previous
#include <cuda_runtime.h>
#include <math.h>

#define BB   8
#define CC   64
#define CR   8
#define HH   64
#define WWD  64
#define NPIX 4096   // HH*WWD
#define NBLK 128    // persistent grid: <= SM count; 128 = BB*16 chunks
#define NTHR 1024

// ---------------- device scratch (static, no allocation) ----------------
__device__ float d_avg[BB * CC];
__device__ float d_maxv[BB * CC];
// PAM fallback scratch (only written when gamma != 0)
__device__ float d_q[BB * CR * NPIX];
__device__ float d_k[BB * CR * NPIX];
__device__ float d_v[BB * CC * NPIX];
__device__ __align__(16) float d_pam[BB * CC * NPIX];
// grid barrier ticket counter (monotonic; safe across graph replays)
__device__ unsigned long long g_bar;

__device__ __forceinline__ void grid_barrier() {
    __syncthreads();
    if (threadIdx.x == 0) {
        __threadfence();
        const unsigned long long t = atomicAdd(&g_bar, 1ULL);
        const unsigned long long release = (t / NBLK + 1ULL) * (unsigned long long)NBLK;
        volatile unsigned long long* p = &g_bar;
        while (*p < release) { }
    }
    __syncthreads();
}

__global__ void __launch_bounds__(NTHR, 1)
k_pcbam(const float* __restrict__ x,
        const float* __restrict__ fc1,   // [CR, C]
        const float* __restrict__ fc2,   // [C, CR]
        const float* __restrict__ qw, const float* __restrict__ qbias,
        const float* __restrict__ kw, const float* __restrict__ kbias,
        const float* __restrict__ vw, const float* __restrict__ vbias,
        const float* __restrict__ gamma,
        const float* __restrict__ sw,    // [2,7,7]
        float* __restrict__ out) {
    const int blk = blockIdx.x;   // 0..127
    const int t   = threadIdx.x;  // 0..1023
    const int b     = blk >> 4;   // batch
    const int chunk = blk & 15;   // 4-row chunk
    const int n0    = chunk << 8;
    const int h0    = chunk << 2;

    // dynamic smem 20 KB: halo-stats partials; PAM fallback overlays att+red.
    extern __shared__ __align__(16) float dyn[];
    float* ps_h = dyn;           // [4 * 640]
    float* pm_h = dyn + 2560;    // [4 * 640]
    float* att  = dyn;           // fallback only [4096]
    float* red  = dyn + NPIX;    // fallback only [1024]

    __shared__ float red_s[32], red_m[32];
    __shared__ float s_sum[CC], s_max[CC], ca[CC];
    __shared__ float h_avg[CR], h_mx[CR];
    __shared__ float tile_avg[10][70], tile_max[10][70];
    __shared__ float wgt[98];
    __shared__ __align__(16) float mask_s[256];

    const float g = gamma[0];
    const int wid = t >> 5, lid = t & 31;

    // ================= Phase A: per-(b,c) mean & max over HW =================
    {
        const int row  = t >> 8;        // 0..3
        const int rtid = t & 255;
        const int bc   = blk * 4 + row;
        const float4* xp = reinterpret_cast<const float4*>(x + (size_t)bc * NPIX);
        float s = 0.0f, m = -INFINITY;
        #pragma unroll
        for (int j = 0; j < 4; j++) {
            const float4 v = xp[rtid + j * 256];
            s += (v.x + v.y) + (v.z + v.w);
            m = fmaxf(m, fmaxf(fmaxf(v.x, v.y), fmaxf(v.z, v.w)));
        }
        #pragma unroll
        for (int off = 16; off; off >>= 1) {
            s += __shfl_down_sync(0xffffffffu, s, off);
            m  = fmaxf(m, __shfl_down_sync(0xffffffffu, m, off));
        }
        if (lid == 0) { red_s[wid] = s; red_m[wid] = m; }
        __syncthreads();
        if (rtid == 0) {
            float ts = 0.0f, tm = -INFINITY;
            #pragma unroll
            for (int w = 0; w < 8; w++) {
                ts += red_s[row * 8 + w];
                tm = fmaxf(tm, red_m[row * 8 + w]);
            }
            d_avg[bc]  = ts * (1.0f / NPIX);
            d_maxv[bc] = tm;
        }
    }

    grid_barrier();   // the ONLY grid sync on the benchmark (g==0) path

    // ---- preload stats + weights, zero conv tile ----
    if (t < 64)                s_sum[t]       = __ldcg(&d_avg[b * CC + t]);
    else if (t < 128)          s_max[t - 64]  = __ldcg(&d_maxv[b * CC + t - 64]);
    else if (t < 226)          wgt[t - 128]   = sw[t - 128];
    for (int i = t; i < 700; i += NTHR) {
        (&tile_avg[0][0])[i] = 0.0f;
        (&tile_max[0][0])[i] = 0.0f;
    }
    __syncthreads();

    // ---- tiny MLP -> ca ----
    if (t < CR) {
        float ha = 0.0f, hm = 0.0f;
        #pragma unroll
        for (int c = 0; c < CC; c++) {
            const float w = fc1[t * CC + c];
            ha += s_sum[c] * w;
            hm += s_max[c] * w;
        }
        h_avg[t] = fmaxf(ha, 0.0f);
        h_mx[t]  = fmaxf(hm, 0.0f);
    }
    __syncthreads();
    if (t < CC) {
        float o = 0.0f;
        #pragma unroll
        for (int r = 0; r < CR; r++)
            o += (h_avg[r] + h_mx[r]) * fc2[t * CR + r];
        ca[t] = 1.0f / (1.0f + __expf(-o));
    }
    __syncthreads();

    // ============ PAM fallback (uniform branch; benchmark: g==0) =============
    if (g != 0.0f) {
        for (int bn = blk * NTHR + t; bn < BB * NPIX; bn += NBLK * NTHR) {
            const int bb = bn >> 12, n = bn & (NPIX - 1);
            const float* xb = x + (size_t)bb * CC * NPIX + n;
            float qa[CR], ka[CR];
            #pragma unroll
            for (int r = 0; r < CR; r++) { qa[r] = qbias[r]; ka[r] = kbias[r]; }
            for (int c = 0; c < CC; c++) {
                const float xv = xb[c * NPIX];
                #pragma unroll
                for (int r = 0; r < CR; r++) {
                    qa[r] += xv * qw[r * CC + c];
                    ka[r] += xv * kw[r * CC + c];
                }
            }
            #pragma unroll
            for (int r = 0; r < CR; r++) {
                d_q[(bb * CR + r) * NPIX + n] = qa[r];
                d_k[(bb * CR + r) * NPIX + n] = ka[r];
            }
        }
        for (int bcn = blk * NTHR + t; bcn < BB * CC * NPIX; bcn += NBLK * NTHR) {
            const int bc = bcn >> 12;
            const int bb = bc >> 6, c = bc & 63, n = bcn & (NPIX - 1);
            const float* xb = x + (size_t)bb * CC * NPIX + n;
            float acc = vbias[c];
            for (int cc = 0; cc < CC; cc++) acc += xb[cc * NPIX] * vw[c * CC + cc];
            d_v[bcn] = acc;
        }
        grid_barrier();
        for (int row = blk; row < BB * NPIX; row += NBLK) {
            const int bb = row >> 12;
            const int i  = row & (NPIX - 1);
            float qr[CR];
            #pragma unroll
            for (int r = 0; r < CR; r++) qr[r] = __ldcg(&d_q[(bb * CR + r) * NPIX + i]);
            float mx = -INFINITY;
            for (int j = t; j < NPIX; j += NTHR) {
                float e = 0.0f;
                #pragma unroll
                for (int r = 0; r < CR; r++) e += qr[r] * __ldcg(&d_k[(bb * CR + r) * NPIX + j]);
                att[j] = e;
                mx = fmaxf(mx, e);
            }
            red[t] = mx; __syncthreads();
            for (int s = NTHR / 2; s; s >>= 1) {
                if (t < s) red[t] = fmaxf(red[t], red[t + s]);
                __syncthreads();
            }
            mx = red[0]; __syncthreads();
            float sum = 0.0f;
            for (int j = t; j < NPIX; j += NTHR) {
                const float e = expf(att[j] - mx);
                att[j] = e;
                sum += e;
            }
            red[t] = sum; __syncthreads();
            for (int s = NTHR / 2; s; s >>= 1) {
                if (t < s) red[t] += red[t + s];
                __syncthreads();
            }
            const float inv = 1.0f / red[0]; __syncthreads();
            for (int c = 0; c < CC; c++) {
                float acc = 0.0f;
                for (int j = t; j < NPIX; j += NTHR)
                    acc += att[j] * __ldcg(&d_v[(bb * CC + c) * NPIX + j]);
                red[t] = acc; __syncthreads();
                for (int s = NTHR / 2; s; s >>= 1) {
                    if (t < s) red[t] += red[t + s];
                    __syncthreads();
                }
                if (t == 0) d_pam[(bb * CC + c) * NPIX + i] = red[0] * inv;
                __syncthreads();
            }
        }
        grid_barrier();
    }

    // ---- halo spatial stats: 2560 items = 4 groups x 640 px, LANE-CONTIGUOUS px ----
    {
        #pragma unroll
        for (int it = 0; it < 3; it++) {
            const int i = it * NTHR + t;
            if (i < 2560) {
                const int grp = i / 640;        // channel group (uniform per 640-run)
                const int px  = i - grp * 640;  // consecutive lanes -> consecutive px
                const int r   = px >> 6;        // halo row 0..9
                const int col = px & 63;
                const int gh  = h0 - 3 + r;
                float s = 0.0f, m = 0.0f;       // 0 = zero padding for OOB rows
                if ((unsigned)gh < (unsigned)HH) {
                    const float* xb = x + (size_t)b * CC * NPIX + gh * WWD + col;
                    m = -INFINITY;
                    #pragma unroll
                    for (int cc = 0; cc < 16; cc++) {
                        const int c = grp * 16 + cc;
                        const float v = __ldg(&xb[c * NPIX]) * ca[c];
                        s += v;
                        m = fmaxf(m, v);
                    }
                }
                ps_h[grp * 640 + px] = s;
                pm_h[grp * 640 + px] = m;
            }
        }
    }
    __syncthreads();
    if (t < 640) {
        const int r = t >> 6, col = t & 63;
        const int gh = h0 - 3 + r;
        float ts = 0.0f, tm = 0.0f;             // zero padding for OOB rows
        if ((unsigned)gh < (unsigned)HH) {
            ts = (ps_h[t] + ps_h[640 + t] + ps_h[1280 + t] + ps_h[1920 + t])
                 * (1.0f / CC);
            tm = fmaxf(fmaxf(pm_h[t], pm_h[640 + t]),
                       fmaxf(pm_h[1280 + t], pm_h[1920 + t]));
        }
        tile_avg[r][col + 3] = ts;
        tile_max[r][col + 3] = tm;
    }
    __syncthreads();

    // ---- 7x7 conv + sigmoid ----
    if (t < 256) {
        const int h = t >> 6, w = t & 63;
        float acc = 0.0f;
        #pragma unroll
        for (int kh = 0; kh < 7; kh++)
            #pragma unroll
            for (int kw2 = 0; kw2 < 7; kw2++)
                acc += tile_avg[h + kh][w + kw2] * wgt[kh * 7 + kw2]
                     + tile_max[h + kh][w + kw2] * wgt[49 + kh * 7 + kw2];
        mask_s[t] = 1.0f / (1.0f + __expf(-acc));
    }
    __syncthreads();

    // ---- final combine: x from L2 (measured faster than smem stash) ----
    {
        const int px4 = t & 63;
        const int c0  = t >> 6;
        const float4 m4 = reinterpret_cast<const float4*>(mask_s)[px4];
        const size_t base4 = (size_t)b * CC * (NPIX / 4) + (size_t)(n0 >> 2) + px4;
        if (g == 0.0f) {
            #pragma unroll
            for (int k = 0; k < 4; k++) {
                const int c = c0 + 16 * k;
                const size_t idx4 = base4 + (size_t)c * (NPIX / 4);
                const float4 xv = reinterpret_cast<const float4*>(x)[idx4];
                const float cav = ca[c];
                float4 o;
                o.x = xv.x * (1.0f + cav * m4.x);
                o.y = xv.y * (1.0f + cav * m4.y);
                o.z = xv.z * (1.0f + cav * m4.z);
                o.w = xv.w * (1.0f + cav * m4.w);
                reinterpret_cast<float4*>(out)[idx4] = o;
            }
        } else {
            #pragma unroll
            for (int k = 0; k < 4; k++) {
                const int c = c0 + 16 * k;
                const size_t idx4 = base4 + (size_t)c * (NPIX / 4);
                const float4 xv = reinterpret_cast<const float4*>(x)[idx4];
                const float4 pv = reinterpret_cast<const float4*>(d_pam)[idx4];
                const float cav = ca[c];
                float4 o;
                o.x = xv.x * (1.0f + cav * m4.x) + g * pv.x;
                o.y = xv.y * (1.0f + cav * m4.y) + g * pv.y;
                o.z = xv.z * (1.0f + cav * m4.z) + g * pv.z;
                o.w = xv.w * (1.0f + cav * m4.w) + g * pv.w;
                reinterpret_cast<float4*>(out)[idx4] = o;
            }
        }
    }
}

// ---------------- launch ----------------
extern "C" void kernel_launch(void* const* d_in, const int* in_sizes, int n_in,
                              void* d_out, int out_size) {
    const float* x     = (const float*)d_in[0];
    const float* fc1_w = (const float*)d_in[1];
    const float* fc2_w = (const float*)d_in[2];
    const float* q_w   = (const float*)d_in[3];
    const float* q_b   = (const float*)d_in[4];
    const float* k_w   = (const float*)d_in[5];
    const float* k_b   = (const float*)d_in[6];
    const float* v_w   = (const float*)d_in[7];
    const float* v_b   = (const float*)d_in[8];
    const float* gamma = (const float*)d_in[9];
    const float* sa_w  = (const float*)d_in[10];
    float* out = (float*)d_out;

    const int dyn_bytes = 2 * 4 * 640 * (int)sizeof(float);   // 20 KB
    k_pcbam<<<NBLK, NTHR, dyn_bytes>>>(x, fc1_w, fc2_w, q_w, q_b, k_w, k_b,
                                       v_w, v_b, gamma, sa_w, out);
}